// round 6
// baseline (speedup 1.0000x reference)
#include <cuda_runtime.h>
#include <cuda_bf16.h>
#include <cuda_fp16.h>

#define NPTS   8192
#define NQ     32768
#define CELLS  16
#define NCELL  (CELLS*CELLS*CELLS)
#define KK     16
#define COUT   64

// ---------------- scratch (static device arrays; no allocation) -------------
__device__ int     d_cellCnt[NCELL];
__device__ int     d_cellStart[NCELL + 1];
__device__ int     d_cellOf[NPTS];
__device__ int     d_rank[NPTS];
__device__ float4  d_pts[NPTS];           // x,y,z, idx-as-float-bits
__device__ int     d_knn[NQ * KK];
__device__ __half2 d_Fph[NPTS * 32];      // features @ ew1[:32] + eb1 (half2)
__device__ float4  d_S0[NPTS];            // vx,vy,vz, mean(F)
__device__ float4  d_S1[NPTS];            // E[F^2], 2E[FA], 2E[FB], 2E[FC]
__device__ float   d_C[9];                // mA,mB,mC,cAA,cBB,cCC,2cAB,2cAC,2cBC
__device__ float   d_W12T[64 * 64];       // (ew2 @ ow1[:64])^T / 16   [c][i]
__device__ float   d_Px[32 * 64];         // separable grid-feat projections
__device__ float   d_Py[32 * 64];
__device__ float   d_Pz[32 * 64];         // includes ob1 + eb2@ow1[:64]

// center-outward column order (sorted by dx^2+dy^2)
__device__ const signed char COL_DX[25] =
    {0, 1,-1, 0, 0, 1, 1,-1,-1, 2,-2, 0, 0, 2, 2,-2,-2, 1, 1,-1,-1, 2, 2,-2,-2};
__device__ const signed char COL_DY[25] =
    {0, 0, 0, 1,-1, 1,-1, 1,-1, 0, 0, 2,-2, 1,-1, 1,-1, 2,-2, 2,-2, 2,-2, 2,-2};

// ---------------- helpers ---------------------------------------------------
__device__ __forceinline__ float ex2a(float x)  { float y; asm("ex2.approx.f32 %0,%1;" : "=f"(y) : "f"(x)); return y; }
__device__ __forceinline__ float rcpa(float x)  { float y; asm("rcp.approx.f32 %0,%1;" : "=f"(y) : "f"(x)); return y; }
__device__ __forceinline__ float rsqa(float x)  { float y; asm("rsqrt.approx.f32 %0,%1;" : "=f"(y) : "f"(x)); return y; }

// gelu_tanh(x) = x * (1 - 1/(2^(x*(2.3021181 + 0.10294919 x^2)) + 1))
__device__ __forceinline__ float gelu_fast(float x) {
    float x2  = x * x;
    float arg = x * fmaf(0.10294919f, x2, 2.3021181f);
    float r   = rcpa(ex2a(arg) + 1.0f);
    return fmaf(-x, r, x);
}

// ================= K_pre: precomputes + bin + per-point projections =========
__global__ void k_pre(const float* __restrict__ verts,
                      const float* __restrict__ feat,
                      const float* __restrict__ gfeat,
                      const float* __restrict__ ew1,
                      const float* __restrict__ eb1,
                      const float* __restrict__ ew2,
                      const float* __restrict__ eb2,
                      const float* __restrict__ ow1,
                      const float* __restrict__ ob1) {
    int b = blockIdx.x, tid = threadIdx.x;
    if (b < 32) {                          // bin points (cellCnt pre-zeroed)
        int i = b * 256 + tid;
        float x = verts[3 * i], y = verts[3 * i + 1], z = verts[3 * i + 2];
        int cx = min(max((int)(x * (float)CELLS), 0), CELLS - 1);
        int cy = min(max((int)(y * (float)CELLS), 0), CELLS - 1);
        int cz = min(max((int)(z * (float)CELLS), 0), CELLS - 1);
        int c = (cx * CELLS + cy) * CELLS + cz;
        d_cellOf[i] = c;
        d_rank[i]   = atomicAdd(&d_cellCnt[c], 1);
        return;
    }
    if (b == 32) {                         // 9 moment constants of ew1 rows 32-34
        if (tid < 9) {
            const float* rows[3] = {ew1 + 2048, ew1 + 2112, ew1 + 2176};
            float acc = 0.0f;
            if (tid < 3) {
                const float* r = rows[tid];
                for (int c = 0; c < 64; ++c) acc += r[c];
                acc *= (1.0f / 64.0f);
            } else if (tid < 6) {
                const float* r = rows[tid - 3];
                for (int c = 0; c < 64; ++c) acc += r[c] * r[c];
                acc *= (1.0f / 64.0f);
            } else {
                int a = (tid == 8) ? 1 : 0;
                int bb = (tid == 6) ? 1 : 2;
                for (int c = 0; c < 64; ++c) acc += rows[a][c] * rows[bb][c];
                acc *= (1.0f / 32.0f);     // 2/64
            }
            d_C[tid] = acc;
        }
        return;
    }
    if (b < 49) {                          // W12T = (ew2 @ ow1[:64])^T / 16
        int idx = (b - 33) * 256 + tid;
        int c = idx >> 6, i = idx & 63;
        float acc = 0.0f;
        for (int k = 0; k < 64; ++k)
            acc += ew2[i * 64 + k] * ow1[k * 64 + c];
        d_W12T[c * 64 + i] = acc * (1.0f / 16.0f);
        return;
    }
    if (b < 73) {                          // separable grid-feat projections
        int idx = (b - 49) * 256 + tid;    // 0..6143
        int axis = idx >> 11, r = (idx >> 6) & 31, c = idx & 63;
        int m0 = (axis == 0) ? r * 1024 : (axis == 1) ? r * 32 : r;
        const float* g = gfeat + m0 * 96 + axis * 32;
        float acc = 0.0f;
        for (int j = 0; j < 32; ++j)
            acc += g[j] * ow1[(64 + axis * 32 + j) * 64 + c];
        if (axis == 0)      d_Px[r * 64 + c] = acc;
        else if (axis == 1) d_Py[r * 64 + c] = acc;
        else {
            float s = ob1[c];
            for (int i = 0; i < 64; ++i) s += eb2[i] * ow1[i * 64 + c];
            d_Pz[r * 64 + c] = acc + s;
        }
        return;
    }
    // fp: warp per point — Fp projection (half2) + per-point LN moments
    int warp = tid >> 5, lane = tid & 31;
    int p = (b - 73) * 8 + warp;
    int c0 = 2 * lane, c1 = c0 + 1;
    float fl = __ldg(&feat[p * 32 + lane]);
    float acc0 = __ldg(&eb1[c0]), acc1 = __ldg(&eb1[c1]);
    #pragma unroll
    for (int i = 0; i < 32; ++i) {
        float fi = __shfl_sync(0xffffffffu, fl, i);
        acc0 = fmaf(fi, __ldg(&ew1[i * 64 + c0]), acc0);
        acc1 = fmaf(fi, __ldg(&ew1[i * 64 + c1]), acc1);
    }
    d_Fph[p * 32 + lane] = __floats2half2_rn(acc0, acc1);
    float A0 = __ldg(&ew1[2048 + c0]), A1 = __ldg(&ew1[2048 + c1]);
    float B0 = __ldg(&ew1[2112 + c0]), B1 = __ldg(&ew1[2112 + c1]);
    float C0 = __ldg(&ew1[2176 + c0]), C1 = __ldg(&ew1[2176 + c1]);
    float pF  = acc0 + acc1;
    float pFF = acc0 * acc0 + acc1 * acc1;
    float pA  = acc0 * A0 + acc1 * A1;
    float pB  = acc0 * B0 + acc1 * B1;
    float pC  = acc0 * C0 + acc1 * C1;
    #pragma unroll
    for (int o = 16; o > 0; o >>= 1) {
        pF  += __shfl_xor_sync(0xffffffffu, pF,  o);
        pFF += __shfl_xor_sync(0xffffffffu, pFF, o);
        pA  += __shfl_xor_sync(0xffffffffu, pA,  o);
        pB  += __shfl_xor_sync(0xffffffffu, pB,  o);
        pC  += __shfl_xor_sync(0xffffffffu, pC,  o);
    }
    if (lane == 0) {
        d_S0[p] = make_float4(__ldg(&verts[3 * p]), __ldg(&verts[3 * p + 1]),
                              __ldg(&verts[3 * p + 2]), pF * (1.0f / 64.0f));
        d_S1[p] = make_float4(pFF * (1.0f / 64.0f), pA * (1.0f / 32.0f),
                              pB * (1.0f / 32.0f),  pC * (1.0f / 32.0f));
    }
}

// =========== scan + scatter fused (1 block, 1024 threads) ===================
__global__ void k_scan_scatter(const float* __restrict__ verts) {
    __shared__ int sc[1024];
    int t = threadIdx.x;
    int c0 = d_cellCnt[4 * t + 0];
    int c1 = d_cellCnt[4 * t + 1];
    int c2 = d_cellCnt[4 * t + 2];
    int c3 = d_cellCnt[4 * t + 3];
    int ts = c0 + c1 + c2 + c3;
    sc[t] = ts;
    __syncthreads();
    for (int off = 1; off < 1024; off <<= 1) {
        int v = (t >= off) ? sc[t - off] : 0;
        __syncthreads();
        sc[t] += v;
        __syncthreads();
    }
    int base = sc[t] - ts;
    d_cellStart[4 * t + 0] = base;
    d_cellStart[4 * t + 1] = base + c0;
    d_cellStart[4 * t + 2] = base + c0 + c1;
    d_cellStart[4 * t + 3] = base + c0 + c1 + c2;
    if (t == 1023) d_cellStart[NCELL] = sc[1023];
    __syncthreads();
    #pragma unroll
    for (int r = 0; r < NPTS / 1024; ++r) {
        int i = r * 1024 + t;
        int dst = d_cellStart[d_cellOf[i]] + d_rank[i];
        d_pts[dst] = make_float4(verts[3 * i], verts[3 * i + 1],
                                 verts[3 * i + 2], __int_as_float(i));
    }
}

// ================= KNN ======================================================
__device__ __forceinline__ void knn_pass(float qx, float qy, float qz,
                                         int cx, int cy, int cz, float Tinit,
                                         float (&bd)[KK], int (&bi)[KK]) {
    #pragma unroll
    for (int t = 0; t < KK; ++t) { bd[t] = Tinit; bi[t] = -1; }
    float worst = Tinit;
    int   wslot = 0;
    const float h = 1.0f / (float)CELLS;

#define SCAN_RANGE(S_, E_)                                                 \
    for (int j_ = (S_); j_ < (E_); ++j_) {                                 \
        float4 p_ = d_pts[j_];                                             \
        float dx_ = p_.x - qx, dy_ = p_.y - qy, dz_ = p_.z - qz;           \
        float d2_ = dx_ * dx_ + dy_ * dy_ + dz_ * dz_;                     \
        if (d2_ < worst) {                                                 \
            int id_ = __float_as_int(p_.w);                                \
            float nw_ = -1.0f; int ns_ = 0;                                \
            _Pragma("unroll")                                              \
            for (int t_ = 0; t_ < KK; ++t_) {                              \
                if (t_ == wslot) { bd[t_] = d2_; bi[t_] = id_; }           \
                if (bd[t_] > nw_) { nw_ = bd[t_]; ns_ = t_; }              \
            }                                                              \
            worst = nw_; wslot = ns_;                                      \
        }                                                                  \
    }

    // Phase 1: cheb-2 neighborhood as center-outward columns, each pruned by
    // its 2D min distance vs current worst (adaptive as worst shrinks).
    {
        int z0 = max(cz - 2, 0), z1e = min(cz + 2, CELLS - 1) + 1;
        #pragma unroll 1
        for (int ci = 0; ci < 25; ++ci) {
            int ax = cx + (int)COL_DX[ci];
            int ay = cy + (int)COL_DY[ci];
            if (ax < 0 || ax > CELLS - 1 || ay < 0 || ay > CELLS - 1) continue;
            float clx = ax * h, cly = ay * h;
            float ddx = fmaxf(fmaxf(clx - qx, qx - clx - h), 0.0f);
            float ddy = fmaxf(fmaxf(cly - qy, qy - cly - h), 0.0f);
            if (ddx * ddx + ddy * ddy >= worst) continue;
            int base = (ax * CELLS + ay) * CELLS;
            int s = d_cellStart[base + z0], e = d_cellStart[base + z1e];
            SCAN_RANGE(s, e)
        }
    }
    // Phase 2: ring expansion until provably complete
    int R = 2;
    while (worst > (R * h) * (R * h) && R < CELLS - 1) {
        ++R;
        int ax0 = max(cx - R, 0), ax1 = min(cx + R, CELLS - 1);
        int ay0 = max(cy - R, 0), ay1 = min(cy + R, CELLS - 1);
        for (int ax = ax0; ax <= ax1; ++ax)
            for (int ay = ay0; ay <= ay1; ++ay) {
                int cxy = max(abs(ax - cx), abs(ay - cy));
                int base = (ax * CELLS + ay) * CELLS;
                if (cxy == R) {
                    int s = d_cellStart[base + max(cz - R, 0)];
                    int e = d_cellStart[base + min(cz + R, CELLS - 1) + 1];
                    SCAN_RANGE(s, e)
                } else {
                    int zl = cz - R, zh = cz + R;
                    if (zl >= 0) {
                        int s = d_cellStart[base + zl], e = d_cellStart[base + zl + 1];
                        SCAN_RANGE(s, e)
                    }
                    if (zh <= CELLS - 1) {
                        int s = d_cellStart[base + zh], e = d_cellStart[base + zh + 1];
                        SCAN_RANGE(s, e)
                    }
                }
            }
    }
#undef SCAN_RANGE
}

__global__ void __launch_bounds__(256) k_knn(const float* __restrict__ gverts) {
    int tid  = blockIdx.x * 256 + threadIdx.x;
    int W    = tid >> 5;
    int lane = tid & 31;
    int lx = lane & 3, ly = (lane >> 2) & 3, lz = lane >> 4;
    int tz = W & 15, ty = (W >> 4) & 7, tx = W >> 7;
    int X = tx * 4 + lx, Y = ty * 4 + ly, Z = tz * 2 + lz;
    int m = (X * 32 + Y) * 32 + Z;

    float qx = gverts[3 * m], qy = gverts[3 * m + 1], qz = gverts[3 * m + 2];
    int cx = min((int)(qx * (float)CELLS), CELLS - 1);
    int cy = min((int)(qy * (float)CELLS), CELLS - 1);
    int cz = min((int)(qz * (float)CELLS), CELLS - 1);

    // density-calibrated threshold, boundary-amplified per clipped axis
    float Tq = 0.010f;
    if (qx < 0.10f || qx > 0.90f) Tq *= 1.5874f;
    if (qy < 0.10f || qy > 0.90f) Tq *= 1.5874f;
    if (qz < 0.10f || qz > 0.90f) Tq *= 1.5874f;

    float bd[KK];
    int   bi[KK];
    // single code instance of knn_pass (retry loop) to keep reg pressure low
    #pragma unroll 1
    for (int attempt = 0; attempt < 2; ++attempt) {
        knn_pass(qx, qy, qz, cx, cy, cz, Tq, bd, bi);
        bool bad = false;
        #pragma unroll
        for (int t = 0; t < KK; ++t) bad |= (bi[t] < 0);
        if (!bad) break;
        Tq = 3.4e38f;
    }

    #pragma unroll
    for (int t = 0; t < KK; ++t) d_knn[m * KK + t] = bi[t];
}

// ================= fused MLP ================================================
__global__ void __launch_bounds__(256) k_mlp(
    const float* __restrict__ gverts, const float* __restrict__ ew1,
    const float* __restrict__ eg1, const float* __restrict__ ebt1,
    const float* __restrict__ og1, const float* __restrict__ obt1,
    const float* __restrict__ ow2, const float* __restrict__ ob2,
    float* __restrict__ out) {

    __shared__ float sAct[8][COUT];
    __shared__ float sPart[4][8][COUT];
    __shared__ float sEdge[8][KK][8];   // [warp][k][rx,ry,rz,mu,rs,jbits,-,-]

    int tid  = threadIdx.x;
    int warp = tid >> 5, lane = tid & 31;
    int m0 = blockIdx.x * 8;
    int m  = m0 + warp;
    int c0 = 2 * lane, c1 = c0 + 1;

    float qx = __ldg(&gverts[3 * m]);
    float qy = __ldg(&gverts[3 * m + 1]);
    float qz = __ldg(&gverts[3 * m + 2]);

    // ---- phase 0: per-edge moment precompute, one edge per lane (<16) ----
    if (lane < KK) {
        int j = __ldg(&d_knn[m * KK + lane]);
        float4 s0 = d_S0[j];
        float4 s1 = d_S1[j];
        float rx = s0.x - qx, ry = s0.y - qy, rz = s0.z - qz;
        float mu = s0.w + rx * d_C[0] + ry * d_C[1] + rz * d_C[2];
        float e2 = s1.x + rx * s1.y + ry * s1.z + rz * s1.w
                 + rx * (rx * d_C[3] + ry * d_C[6] + rz * d_C[7])
                 + ry * ry * d_C[4] + rz * (ry * d_C[8] + rz * d_C[5]);
        float rs = rsqa(e2 - mu * mu + 1e-5f);
        float* se = sEdge[warp][lane];
        se[0] = rx; se[1] = ry; se[2] = rz; se[3] = mu; se[4] = rs;
        ((int*)se)[5] = j;
    }
    __syncwarp();

    // ---- phase 1: edge loop (Fp in half2 — 1 wavefront per edge) ----
    float wp00 = __ldg(&ew1[2048 + c0]), wp01 = __ldg(&ew1[2048 + c1]);
    float wp10 = __ldg(&ew1[2112 + c0]), wp11 = __ldg(&ew1[2112 + c1]);
    float wp20 = __ldg(&ew1[2176 + c0]), wp21 = __ldg(&ew1[2176 + c1]);
    float ge0 = __ldg(&eg1[c0]),  ge1 = __ldg(&eg1[c1]);
    float gb0 = __ldg(&ebt1[c0]), gb1 = __ldg(&ebt1[c1]);

    float a0 = 0.0f, a1 = 0.0f;
    #pragma unroll 4
    for (int k = 0; k < KK; ++k) {
        const float* se = sEdge[warp][k];
        float4 v0 = *(const float4*)se;          // rx,ry,rz,mu
        float2 v1 = *(const float2*)(se + 4);    // rs, jbits
        int j = __float_as_int(v1.y);
        float2 f = __half22float2(d_Fph[j * 32 + lane]);
        float h0 = f.x + v0.x * wp00 + v0.y * wp10 + v0.z * wp20;
        float h1 = f.y + v0.x * wp01 + v0.y * wp11 + v0.z * wp21;
        float rsg0 = v1.x * ge0, rsg1 = v1.x * ge1;
        float n0 = fmaf(h0, rsg0, fmaf(-v0.w, rsg0, gb0));
        float n1 = fmaf(h1, rsg1, fmaf(-v0.w, rsg1, gb1));
        a0 += gelu_fast(n0);
        a1 += gelu_fast(n1);
    }
    sAct[warp][c0] = a0;
    sAct[warp][c1] = a1;
    __syncthreads();

    // remapped split-matvec indices: warp lanes cover 8 full cache lines
    int g = tid & 3, cc = tid >> 2;

    // ---- phase 2: block matvec @ W12T ----
    {
        float acc[8];
        #pragma unroll
        for (int q = 0; q < 8; ++q) acc[q] = 0.0f;
        #pragma unroll
        for (int i4 = 0; i4 < 4; ++i4) {
            float4 w = __ldg((const float4*)&d_W12T[cc * 64 + g * 16 + i4 * 4]);
            #pragma unroll
            for (int q = 0; q < 8; ++q) {
                float4 a = *(const float4*)&sAct[q][g * 16 + i4 * 4];
                acc[q] += a.x * w.x + a.y * w.y + a.z * w.z + a.w * w.w;
            }
        }
        #pragma unroll
        for (int q = 0; q < 8; ++q) sPart[g][q][cc] = acc[q];
    }
    __syncthreads();

    // ---- phase 3: combine + grid-feat tables + LN + gelu (warp per query) --
    {
        int X = m >> 10, Y = (m >> 5) & 31, Z = m & 31;
        float2 px = *(const float2*)&d_Px[X * 64 + c0];
        float2 py = *(const float2*)&d_Py[Y * 64 + c0];
        float2 pz = *(const float2*)&d_Pz[Z * 64 + c0];
        float o0 = px.x + py.x + pz.x
                 + sPart[0][warp][c0] + sPart[1][warp][c0]
                 + sPart[2][warp][c0] + sPart[3][warp][c0];
        float o1 = px.y + py.y + pz.y
                 + sPart[0][warp][c1] + sPart[1][warp][c1]
                 + sPart[2][warp][c1] + sPart[3][warp][c1];
        float s  = o0 + o1;
        float s2 = o0 * o0 + o1 * o1;
        #pragma unroll
        for (int o = 16; o > 0; o >>= 1) {
            s  += __shfl_xor_sync(0xffffffffu, s,  o);
            s2 += __shfl_xor_sync(0xffffffffu, s2, o);
        }
        float mu  = s * (1.0f / 64.0f);
        float var = s2 * (1.0f / 64.0f) - mu * mu;
        float rs  = rsqa(var + 1e-5f);
        float oge0 = __ldg(&og1[c0]),  oge1 = __ldg(&og1[c1]);
        float ogb0 = __ldg(&obt1[c0]), ogb1 = __ldg(&obt1[c1]);
        o0 = gelu_fast((o0 - mu) * rs * oge0 + ogb0);
        o1 = gelu_fast((o1 - mu) * rs * oge1 + ogb1);
        __syncthreads();
        sAct[warp][c0] = o0;
        sAct[warp][c1] = o1;
    }
    __syncthreads();

    // ---- phase 4: block matvec @ ow2 (input layout [i][c] → transposed read
    //      per output channel cc; lanes cover 8 full lines via remap) ----
    {
        float acc[8];
        #pragma unroll
        for (int q = 0; q < 8; ++q) acc[q] = 0.0f;
        #pragma unroll
        for (int i4 = 0; i4 < 4; ++i4) {
            int i0 = g * 16 + i4 * 4;
            float w0 = __ldg(&ow2[(i0 + 0) * 64 + cc]);
            float w1 = __ldg(&ow2[(i0 + 1) * 64 + cc]);
            float w2 = __ldg(&ow2[(i0 + 2) * 64 + cc]);
            float w3 = __ldg(&ow2[(i0 + 3) * 64 + cc]);
            #pragma unroll
            for (int q = 0; q < 8; ++q) {
                float4 a = *(const float4*)&sAct[q][i0];
                acc[q] += a.x * w0 + a.y * w1 + a.z * w2 + a.w * w3;
            }
        }
        #pragma unroll
        for (int q = 0; q < 8; ++q) sPart[g][q][cc] = acc[q];
    }
    __syncthreads();

    // ---- phase 5: final combine + bias + store ----
    float bias = __ldg(&ob2[cc]);
    #pragma unroll
    for (int rep = 0; rep < 2; ++rep) {
        int q = g + rep * 4;
        float v = sPart[0][q][cc] + sPart[1][q][cc]
                + sPart[2][q][cc] + sPart[3][q][cc] + bias;
        out[(m0 + q) * 64 + cc] = v;
    }
}

// ---------------- launch -----------------------------------------------------
extern "C" void kernel_launch(void* const* d_in, const int* in_sizes, int n_in,
                              void* d_out, int out_size) {
    const float* vertices = (const float*)d_in[0];
    const float* features = (const float*)d_in[1];
    const float* gverts   = (const float*)d_in[2];
    const float* gfeat    = (const float*)d_in[3];
    const float* ew1      = (const float*)d_in[4];
    const float* eb1      = (const float*)d_in[5];
    const float* eg1      = (const float*)d_in[6];
    const float* ebt1     = (const float*)d_in[7];
    const float* ew2      = (const float*)d_in[8];
    const float* eb2      = (const float*)d_in[9];
    const float* ow1      = (const float*)d_in[10];
    const float* ob1      = (const float*)d_in[11];
    const float* og1      = (const float*)d_in[12];
    const float* obt1     = (const float*)d_in[13];
    const float* ow2      = (const float*)d_in[14];
    const float* ob2      = (const float*)d_in[15];
    float* out = (float*)d_out;

    void* cntPtr = nullptr;
    cudaGetSymbolAddress(&cntPtr, d_cellCnt);
    cudaMemsetAsync(cntPtr, 0, NCELL * sizeof(int));

    k_pre <<<73 + NPTS / 8, 256>>>(vertices, features, gfeat, ew1, eb1, ew2,
                                   eb2, ow1, ob1);
    k_scan_scatter<<<1, 1024>>>(vertices);
    k_knn <<<NQ / 256, 256>>>(gverts);
    k_mlp <<<NQ / 8, 256>>>(gverts, ew1, eg1, ebt1, og1, obt1, ow2, ob2, out);
}

// round 9
// speedup vs baseline: 1.3974x; 1.3974x over previous
#include <cuda_runtime.h>
#include <cuda_bf16.h>
#include <cuda_fp16.h>

#define NPTS   8192
#define NQ     32768
#define CELLS  16
#define NCELL  (CELLS*CELLS*CELLS)
#define KK     16
#define COUT   64

// ---------------- scratch (static device arrays; no allocation) -------------
__device__ int     d_cellCnt[NCELL];
__device__ int     d_cellStart[NCELL + 1];
__device__ int     d_cellOf[NPTS];
__device__ int     d_rank[NPTS];
__device__ float4  d_pts[NPTS];           // x,y,z, idx-as-float-bits
__device__ int     d_knn[NQ * KK];
__device__ __half2 d_Fph[NPTS * 32];      // features @ ew1[:32] + eb1 (half2)
__device__ float4  d_S0[NPTS];            // vx,vy,vz, mean(F)
__device__ float4  d_S1[NPTS];            // E[F^2], 2E[FA], 2E[FB], 2E[FC]
__device__ float   d_C[9];                // mA,mB,mC,cAA,cBB,cCC,2cAB,2cAC,2cBC
__device__ float   d_W12I[64 * 64];       // interleaved (ew2@ow1[:64])^T/16
__device__ float   d_ow2I[64 * 64];       // interleaved ow2^T
__device__ float   d_Px[32 * 64];         // separable grid-feat projections
__device__ float   d_Py[32 * 64];
__device__ float   d_Pz[32 * 64];         // includes ob1 + eb2@ow1[:64]

// center-outward column order (sorted by dx^2+dy^2)
__device__ const signed char COL_DX[25] =
    {0, 1,-1, 0, 0, 1, 1,-1,-1, 2,-2, 0, 0, 2, 2,-2,-2, 1, 1,-1,-1, 2, 2,-2,-2};
__device__ const signed char COL_DY[25] =
    {0, 0, 0, 1,-1, 1,-1, 1,-1, 0, 0, 2,-2, 1,-1, 1,-1, 2,-2, 2,-2, 2,-2, 2,-2};

// ---------------- helpers ---------------------------------------------------
__device__ __forceinline__ float ex2a(float x)  { float y; asm("ex2.approx.f32 %0,%1;" : "=f"(y) : "f"(x)); return y; }
__device__ __forceinline__ float rcpa(float x)  { float y; asm("rcp.approx.f32 %0,%1;" : "=f"(y) : "f"(x)); return y; }
__device__ __forceinline__ float rsqa(float x)  { float y; asm("rsqrt.approx.f32 %0,%1;" : "=f"(y) : "f"(x)); return y; }

// gelu_tanh(x) = x * (1 - 1/(2^(x*(2.3021181 + 0.10294919 x^2)) + 1))
__device__ __forceinline__ float gelu_fast(float x) {
    float x2  = x * x;
    float arg = x * fmaf(0.10294919f, x2, 2.3021181f);
    float r   = rcpa(ex2a(arg) + 1.0f);
    return fmaf(-x, r, x);
}

// ================= K_pre: precomputes + bin + per-point projections =========
__global__ void k_pre(const float* __restrict__ verts,
                      const float* __restrict__ feat,
                      const float* __restrict__ gfeat,
                      const float* __restrict__ ew1,
                      const float* __restrict__ eb1,
                      const float* __restrict__ ew2,
                      const float* __restrict__ eb2,
                      const float* __restrict__ ow1,
                      const float* __restrict__ ob1,
                      const float* __restrict__ ow2) {
    int b = blockIdx.x, tid = threadIdx.x;
    if (b < 32) {                          // bin points (cellCnt pre-zeroed)
        int i = b * 256 + tid;
        float x = verts[3 * i], y = verts[3 * i + 1], z = verts[3 * i + 2];
        int cx = min(max((int)(x * (float)CELLS), 0), CELLS - 1);
        int cy = min(max((int)(y * (float)CELLS), 0), CELLS - 1);
        int cz = min(max((int)(z * (float)CELLS), 0), CELLS - 1);
        int c = (cx * CELLS + cy) * CELLS + cz;
        d_cellOf[i] = c;
        d_rank[i]   = atomicAdd(&d_cellCnt[c], 1);
        return;
    }
    if (b == 32) {                         // 9 moment constants of ew1 rows 32-34
        if (tid < 9) {
            const float* rows[3] = {ew1 + 2048, ew1 + 2112, ew1 + 2176};
            float acc = 0.0f;
            if (tid < 3) {
                const float* r = rows[tid];
                for (int c = 0; c < 64; ++c) acc += r[c];
                acc *= (1.0f / 64.0f);
            } else if (tid < 6) {
                const float* r = rows[tid - 3];
                for (int c = 0; c < 64; ++c) acc += r[c] * r[c];
                acc *= (1.0f / 64.0f);
            } else {
                int a = (tid == 8) ? 1 : 0;
                int bb = (tid == 6) ? 1 : 2;
                for (int c = 0; c < 64; ++c) acc += rows[a][c] * rows[bb][c];
                acc *= (1.0f / 32.0f);     // 2/64
            }
            d_C[tid] = acc;
        }
        return;
    }
    if (b < 49) {       // W12I interleaved: thread(g,cc) step i4 reads float4 at
                        // ((g*4+i4)*64+cc)*4 ; element k = (ew2@ow1)[g*16+i4*4+k][cc]/16
        int idx = (b - 33) * 256 + tid;    // 0..4095
        int n = idx >> 2, k = idx & 3;
        int r = n >> 6, cc = n & 63;       // r = g*4+i4
        int i = r * 4 + k;                 // input-channel index
        float acc = 0.0f;
        for (int t = 0; t < 64; ++t)
            acc += ew2[i * 64 + t] * ow1[t * 64 + cc];
        d_W12I[idx] = acc * (1.0f / 16.0f);
        return;
    }
    if (b < 65) {                          // ow2 interleaved, same scheme
        int idx = (b - 49) * 256 + tid;
        int n = idx >> 2, k = idx & 3;
        int r = n >> 6, cc = n & 63;
        d_ow2I[idx] = ow2[(r * 4 + k) * 64 + cc];
        return;
    }
    if (b < 89) {                          // separable grid-feat projections
        int idx = (b - 65) * 256 + tid;    // 0..6143
        int axis = idx >> 11, r = (idx >> 6) & 31, c = idx & 63;
        int m0 = (axis == 0) ? r * 1024 : (axis == 1) ? r * 32 : r;
        const float* g = gfeat + m0 * 96 + axis * 32;
        float acc = 0.0f;
        for (int j = 0; j < 32; ++j)
            acc += g[j] * ow1[(64 + axis * 32 + j) * 64 + c];
        if (axis == 0)      d_Px[r * 64 + c] = acc;
        else if (axis == 1) d_Py[r * 64 + c] = acc;
        else {
            float s = ob1[c];
            for (int i = 0; i < 64; ++i) s += eb2[i] * ow1[i * 64 + c];
            d_Pz[r * 64 + c] = acc + s;
        }
        return;
    }
    // fp: warp per point — Fp projection (half2) + per-point LN moments
    int warp = tid >> 5, lane = tid & 31;
    int p = (b - 89) * 8 + warp;
    int c0 = 2 * lane, c1 = c0 + 1;
    float fl = __ldg(&feat[p * 32 + lane]);
    float acc0 = __ldg(&eb1[c0]), acc1 = __ldg(&eb1[c1]);
    #pragma unroll
    for (int i = 0; i < 32; ++i) {
        float fi = __shfl_sync(0xffffffffu, fl, i);
        acc0 = fmaf(fi, __ldg(&ew1[i * 64 + c0]), acc0);
        acc1 = fmaf(fi, __ldg(&ew1[i * 64 + c1]), acc1);
    }
    d_Fph[p * 32 + lane] = __floats2half2_rn(acc0, acc1);
    float A0 = __ldg(&ew1[2048 + c0]), A1 = __ldg(&ew1[2048 + c1]);
    float B0 = __ldg(&ew1[2112 + c0]), B1 = __ldg(&ew1[2112 + c1]);
    float C0 = __ldg(&ew1[2176 + c0]), C1 = __ldg(&ew1[2176 + c1]);
    float pF  = acc0 + acc1;
    float pFF = acc0 * acc0 + acc1 * acc1;
    float pA  = acc0 * A0 + acc1 * A1;
    float pB  = acc0 * B0 + acc1 * B1;
    float pC  = acc0 * C0 + acc1 * C1;
    #pragma unroll
    for (int o = 16; o > 0; o >>= 1) {
        pF  += __shfl_xor_sync(0xffffffffu, pF,  o);
        pFF += __shfl_xor_sync(0xffffffffu, pFF, o);
        pA  += __shfl_xor_sync(0xffffffffu, pA,  o);
        pB  += __shfl_xor_sync(0xffffffffu, pB,  o);
        pC  += __shfl_xor_sync(0xffffffffu, pC,  o);
    }
    if (lane == 0) {
        d_S0[p] = make_float4(__ldg(&verts[3 * p]), __ldg(&verts[3 * p + 1]),
                              __ldg(&verts[3 * p + 2]), pF * (1.0f / 64.0f));
        d_S1[p] = make_float4(pFF * (1.0f / 64.0f), pA * (1.0f / 32.0f),
                              pB * (1.0f / 32.0f),  pC * (1.0f / 32.0f));
    }
}

// =========== scan + scatter fused (1 block, 1024 threads) ===================
__global__ void k_scan_scatter(const float* __restrict__ verts) {
    __shared__ int sc[1024];
    int t = threadIdx.x;
    int c0 = d_cellCnt[4 * t + 0];
    int c1 = d_cellCnt[4 * t + 1];
    int c2 = d_cellCnt[4 * t + 2];
    int c3 = d_cellCnt[4 * t + 3];
    int ts = c0 + c1 + c2 + c3;
    sc[t] = ts;
    __syncthreads();
    for (int off = 1; off < 1024; off <<= 1) {
        int v = (t >= off) ? sc[t - off] : 0;
        __syncthreads();
        sc[t] += v;
        __syncthreads();
    }
    int base = sc[t] - ts;
    d_cellStart[4 * t + 0] = base;
    d_cellStart[4 * t + 1] = base + c0;
    d_cellStart[4 * t + 2] = base + c0 + c1;
    d_cellStart[4 * t + 3] = base + c0 + c1 + c2;
    if (t == 1023) d_cellStart[NCELL] = sc[1023];
    __syncthreads();
    #pragma unroll
    for (int r = 0; r < NPTS / 1024; ++r) {
        int i = r * 1024 + t;
        int dst = d_cellStart[d_cellOf[i]] + d_rank[i];
        d_pts[dst] = make_float4(verts[3 * i], verts[3 * i + 1],
                                 verts[3 * i + 2], __int_as_float(i));
    }
}

// ================= KNN ======================================================
__device__ __forceinline__ void knn_pass(float qx, float qy, float qz,
                                         int cx, int cy, int cz, float Tinit,
                                         float (&bd)[KK], int (&bi)[KK]) {
    #pragma unroll
    for (int t = 0; t < KK; ++t) { bd[t] = Tinit; bi[t] = -1; }
    float worst = Tinit;
    int   wslot = 0;
    const float h = 1.0f / (float)CELLS;

#define SCAN_RANGE(S_, E_)                                                 \
    for (int j_ = (S_); j_ < (E_); ++j_) {                                 \
        float4 p_ = d_pts[j_];                                             \
        float dx_ = p_.x - qx, dy_ = p_.y - qy, dz_ = p_.z - qz;           \
        float d2_ = dx_ * dx_ + dy_ * dy_ + dz_ * dz_;                     \
        if (d2_ < worst) {                                                 \
            int id_ = __float_as_int(p_.w);                                \
            float nw_ = -1.0f; int ns_ = 0;                                \
            _Pragma("unroll")                                              \
            for (int t_ = 0; t_ < KK; ++t_) {                              \
                if (t_ == wslot) { bd[t_] = d2_; bi[t_] = id_; }           \
                if (bd[t_] > nw_) { nw_ = bd[t_]; ns_ = t_; }              \
            }                                                              \
            worst = nw_; wslot = ns_;                                      \
        }                                                                  \
    }

    // Phase 1: cheb-2 neighborhood as center-outward columns, each pruned by
    // its 2D min distance vs current worst (adaptive as worst shrinks).
    {
        int z0 = max(cz - 2, 0), z1e = min(cz + 2, CELLS - 1) + 1;
        #pragma unroll 1
        for (int ci = 0; ci < 25; ++ci) {
            int ax = cx + (int)COL_DX[ci];
            int ay = cy + (int)COL_DY[ci];
            if (ax < 0 || ax > CELLS - 1 || ay < 0 || ay > CELLS - 1) continue;
            float clx = ax * h, cly = ay * h;
            float ddx = fmaxf(fmaxf(clx - qx, qx - clx - h), 0.0f);
            float ddy = fmaxf(fmaxf(cly - qy, qy - cly - h), 0.0f);
            if (ddx * ddx + ddy * ddy >= worst) continue;
            int base = (ax * CELLS + ay) * CELLS;
            int s = d_cellStart[base + z0], e = d_cellStart[base + z1e];
            SCAN_RANGE(s, e)
        }
    }
    // Phase 2: ring expansion until provably complete
    int R = 2;
    while (worst > (R * h) * (R * h) && R < CELLS - 1) {
        ++R;
        int ax0 = max(cx - R, 0), ax1 = min(cx + R, CELLS - 1);
        int ay0 = max(cy - R, 0), ay1 = min(cy + R, CELLS - 1);
        for (int ax = ax0; ax <= ax1; ++ax)
            for (int ay = ay0; ay <= ay1; ++ay) {
                int cxy = max(abs(ax - cx), abs(ay - cy));
                int base = (ax * CELLS + ay) * CELLS;
                if (cxy == R) {
                    int s = d_cellStart[base + max(cz - R, 0)];
                    int e = d_cellStart[base + min(cz + R, CELLS - 1) + 1];
                    SCAN_RANGE(s, e)
                } else {
                    int zl = cz - R, zh = cz + R;
                    if (zl >= 0) {
                        int s = d_cellStart[base + zl], e = d_cellStart[base + zl + 1];
                        SCAN_RANGE(s, e)
                    }
                    if (zh <= CELLS - 1) {
                        int s = d_cellStart[base + zh], e = d_cellStart[base + zh + 1];
                        SCAN_RANGE(s, e)
                    }
                }
            }
    }
#undef SCAN_RANGE
}

__global__ void __launch_bounds__(256) k_knn(const float* __restrict__ gverts) {
    int tid  = blockIdx.x * 256 + threadIdx.x;
    int W    = tid >> 5;
    int lane = tid & 31;
    int lx = lane & 3, ly = (lane >> 2) & 3, lz = lane >> 4;
    int tz = W & 15, ty = (W >> 4) & 7, tx = W >> 7;
    int X = tx * 4 + lx, Y = ty * 4 + ly, Z = tz * 2 + lz;
    int m = (X * 32 + Y) * 32 + Z;

    float qx = gverts[3 * m], qy = gverts[3 * m + 1], qz = gverts[3 * m + 2];
    int cx = min((int)(qx * (float)CELLS), CELLS - 1);
    int cy = min((int)(qy * (float)CELLS), CELLS - 1);
    int cz = min((int)(qz * (float)CELLS), CELLS - 1);

    // density-calibrated threshold, boundary-amplified per clipped axis
    float Tq = 0.010f;
    if (qx < 0.10f || qx > 0.90f) Tq *= 1.5874f;
    if (qy < 0.10f || qy > 0.90f) Tq *= 1.5874f;
    if (qz < 0.10f || qz > 0.90f) Tq *= 1.5874f;

    float bd[KK];
    int   bi[KK];
    // single code instance of knn_pass (retry loop) to keep reg pressure low
    #pragma unroll 1
    for (int attempt = 0; attempt < 2; ++attempt) {
        knn_pass(qx, qy, qz, cx, cy, cz, Tq, bd, bi);
        bool bad = false;
        #pragma unroll
        for (int t = 0; t < KK; ++t) bad |= (bi[t] < 0);
        if (!bad) break;
        Tq = 3.4e38f;
    }

    #pragma unroll
    for (int t = 0; t < KK; ++t) d_knn[m * KK + t] = bi[t];
}

// ================= fused MLP ================================================
__global__ void __launch_bounds__(256) k_mlp(
    const float* __restrict__ gverts, const float* __restrict__ ew1,
    const float* __restrict__ eg1, const float* __restrict__ ebt1,
    const float* __restrict__ og1, const float* __restrict__ obt1,
    const float* __restrict__ ob2, float* __restrict__ out) {

    __shared__ float sAct[8][COUT];
    __shared__ float sPart[4][8][COUT];
    __shared__ float sEdge[8][KK][8];   // [warp][k][rx,ry,rz,mu,rs,jbits,-,-]

    int tid  = threadIdx.x;
    int warp = tid >> 5, lane = tid & 31;
    int m0 = blockIdx.x * 8;
    int m  = m0 + warp;
    int c0 = 2 * lane, c1 = c0 + 1;

    float qx = __ldg(&gverts[3 * m]);
    float qy = __ldg(&gverts[3 * m + 1]);
    float qz = __ldg(&gverts[3 * m + 2]);

    // ---- phase 0: per-edge moment precompute, one edge per lane (<16) ----
    if (lane < KK) {
        int j = __ldg(&d_knn[m * KK + lane]);
        float4 s0 = d_S0[j];
        float4 s1 = d_S1[j];
        float rx = s0.x - qx, ry = s0.y - qy, rz = s0.z - qz;
        float mu = s0.w + rx * d_C[0] + ry * d_C[1] + rz * d_C[2];
        float e2 = s1.x + rx * s1.y + ry * s1.z + rz * s1.w
                 + rx * (rx * d_C[3] + ry * d_C[6] + rz * d_C[7])
                 + ry * ry * d_C[4] + rz * (ry * d_C[8] + rz * d_C[5]);
        float rs = rsqa(e2 - mu * mu + 1e-5f);
        float* se = sEdge[warp][lane];
        se[0] = rx; se[1] = ry; se[2] = rz; se[3] = mu; se[4] = rs;
        ((int*)se)[5] = j;
    }
    __syncwarp();

    // ---- phase 1: edge loop (Fp in half2 — 1 wavefront per edge) ----
    float wp00 = __ldg(&ew1[2048 + c0]), wp01 = __ldg(&ew1[2048 + c1]);
    float wp10 = __ldg(&ew1[2112 + c0]), wp11 = __ldg(&ew1[2112 + c1]);
    float wp20 = __ldg(&ew1[2176 + c0]), wp21 = __ldg(&ew1[2176 + c1]);
    float ge0 = __ldg(&eg1[c0]),  ge1 = __ldg(&eg1[c1]);
    float gb0 = __ldg(&ebt1[c0]), gb1 = __ldg(&ebt1[c1]);

    float a0 = 0.0f, a1 = 0.0f;
    #pragma unroll 4
    for (int k = 0; k < KK; ++k) {
        const float* se = sEdge[warp][k];
        float4 v0 = *(const float4*)se;          // rx,ry,rz,mu
        float2 v1 = *(const float2*)(se + 4);    // rs, jbits
        int j = __float_as_int(v1.y);
        float2 f = __half22float2(d_Fph[j * 32 + lane]);
        float h0 = f.x + v0.x * wp00 + v0.y * wp10 + v0.z * wp20;
        float h1 = f.y + v0.x * wp01 + v0.y * wp11 + v0.z * wp21;
        float rsg0 = v1.x * ge0, rsg1 = v1.x * ge1;
        float n0 = fmaf(h0, rsg0, fmaf(-v0.w, rsg0, gb0));
        float n1 = fmaf(h1, rsg1, fmaf(-v0.w, rsg1, gb1));
        a0 += gelu_fast(n0);
        a1 += gelu_fast(n1);
    }
    sAct[warp][c0] = a0;
    sAct[warp][c1] = a1;
    __syncthreads();

    // R4 conflict-free mapping: g uniform per warp, cc consecutive
    int g = tid >> 6, cc = tid & 63;

    // ---- phase 2: block matvec @ W12I (interleaved; 512B contiguous/warp) --
    {
        float acc[8];
        #pragma unroll
        for (int q = 0; q < 8; ++q) acc[q] = 0.0f;
        #pragma unroll
        for (int i4 = 0; i4 < 4; ++i4) {
            float4 w = __ldg((const float4*)&d_W12I[((g * 4 + i4) * 64 + cc) * 4]);
            #pragma unroll
            for (int q = 0; q < 8; ++q) {
                float4 a = *(const float4*)&sAct[q][g * 16 + i4 * 4];
                acc[q] += a.x * w.x + a.y * w.y + a.z * w.z + a.w * w.w;
            }
        }
        #pragma unroll
        for (int q = 0; q < 8; ++q) sPart[g][q][cc] = acc[q];
    }
    __syncthreads();

    // ---- phase 3: combine + grid-feat tables + LN + gelu (warp per query) --
    {
        int X = m >> 10, Y = (m >> 5) & 31, Z = m & 31;
        float2 px = *(const float2*)&d_Px[X * 64 + c0];
        float2 py = *(const float2*)&d_Py[Y * 64 + c0];
        float2 pz = *(const float2*)&d_Pz[Z * 64 + c0];
        float o0 = px.x + py.x + pz.x
                 + sPart[0][warp][c0] + sPart[1][warp][c0]
                 + sPart[2][warp][c0] + sPart[3][warp][c0];
        float o1 = px.y + py.y + pz.y
                 + sPart[0][warp][c1] + sPart[1][warp][c1]
                 + sPart[2][warp][c1] + sPart[3][warp][c1];
        float s  = o0 + o1;
        float s2 = o0 * o0 + o1 * o1;
        #pragma unroll
        for (int o = 16; o > 0; o >>= 1) {
            s  += __shfl_xor_sync(0xffffffffu, s,  o);
            s2 += __shfl_xor_sync(0xffffffffu, s2, o);
        }
        float mu  = s * (1.0f / 64.0f);
        float var = s2 * (1.0f / 64.0f) - mu * mu;
        float rs  = rsqa(var + 1e-5f);
        float oge0 = __ldg(&og1[c0]),  oge1 = __ldg(&og1[c1]);
        float ogb0 = __ldg(&obt1[c0]), ogb1 = __ldg(&obt1[c1]);
        o0 = gelu_fast((o0 - mu) * rs * oge0 + ogb0);
        o1 = gelu_fast((o1 - mu) * rs * oge1 + ogb1);
        __syncthreads();
        sAct[warp][c0] = o0;
        sAct[warp][c1] = o1;
    }
    __syncthreads();

    // ---- phase 4: block matvec @ ow2I (interleaved) ----
    {
        float acc[8];
        #pragma unroll
        for (int q = 0; q < 8; ++q) acc[q] = 0.0f;
        #pragma unroll
        for (int i4 = 0; i4 < 4; ++i4) {
            float4 w = __ldg((const float4*)&d_ow2I[((g * 4 + i4) * 64 + cc) * 4]);
            #pragma unroll
            for (int q = 0; q < 8; ++q) {
                float4 a = *(const float4*)&sAct[q][g * 16 + i4 * 4];
                acc[q] += a.x * w.x + a.y * w.y + a.z * w.z + a.w * w.w;
            }
        }
        #pragma unroll
        for (int q = 0; q < 8; ++q) sPart[g][q][cc] = acc[q];
    }
    __syncthreads();

    // ---- phase 5: final combine + bias + store ----
    float bias = __ldg(&ob2[cc]);
    #pragma unroll
    for (int rep = 0; rep < 2; ++rep) {
        int q = g + rep * 4;
        float v = sPart[0][q][cc] + sPart[1][q][cc]
                + sPart[2][q][cc] + sPart[3][q][cc] + bias;
        out[(m0 + q) * 64 + cc] = v;
    }
}

// ---------------- launch -----------------------------------------------------
extern "C" void kernel_launch(void* const* d_in, const int* in_sizes, int n_in,
                              void* d_out, int out_size) {
    const float* vertices = (const float*)d_in[0];
    const float* features = (const float*)d_in[1];
    const float* gverts   = (const float*)d_in[2];
    const float* gfeat    = (const float*)d_in[3];
    const float* ew1      = (const float*)d_in[4];
    const float* eb1      = (const float*)d_in[5];
    const float* eg1      = (const float*)d_in[6];
    const float* ebt1     = (const float*)d_in[7];
    const float* ew2      = (const float*)d_in[8];
    const float* eb2      = (const float*)d_in[9];
    const float* ow1      = (const float*)d_in[10];
    const float* ob1      = (const float*)d_in[11];
    const float* og1      = (const float*)d_in[12];
    const float* obt1     = (const float*)d_in[13];
    const float* ow2      = (const float*)d_in[14];
    const float* ob2      = (const float*)d_in[15];
    float* out = (float*)d_out;

    void* cntPtr = nullptr;
    cudaGetSymbolAddress(&cntPtr, d_cellCnt);
    cudaMemsetAsync(cntPtr, 0, NCELL * sizeof(int));

    k_pre <<<89 + NPTS / 8, 256>>>(vertices, features, gfeat, ew1, eb1, ew2,
                                   eb2, ow1, ob1, ow2);
    k_scan_scatter<<<1, 1024>>>(vertices);
    k_knn <<<NQ / 256, 256>>>(gverts);
    k_mlp <<<NQ / 8, 256>>>(gverts, ew1, eg1, ebt1, og1, obt1, ob2, out);
}

// round 10
// speedup vs baseline: 1.5023x; 1.0751x over previous
#include <cuda_runtime.h>
#include <cuda_bf16.h>
#include <cuda_fp16.h>

#define NPTS   8192
#define NQ     32768
#define CELLS  16
#define NCELL  (CELLS*CELLS*CELLS)
#define KK     16
#define COUT   64

// ---------------- scratch (static device arrays; no allocation) -------------
__device__ int     d_cellCnt[NCELL];
__device__ int     d_cellStart[NCELL + 1];
__device__ int     d_cellOf[NPTS];
__device__ int     d_rank[NPTS];
__device__ float4  d_pts[NPTS];           // x,y,z, idx-as-float-bits
__device__ int     d_knn[NQ * KK];
__device__ __half2 d_Fph[NPTS * 32];      // features @ ew1[:32] + eb1 (half2)
__device__ float4  d_S0[NPTS];            // vx,vy,vz, mean(F)
__device__ float4  d_S1[NPTS];            // E[F^2], 2E[FA], 2E[FB], 2E[FC]
__device__ float   d_C[9];                // mA,mB,mC,cAA,cBB,cCC,2cAB,2cAC,2cBC
__device__ float   d_W12I[64 * 64];       // interleaved (ew2@ow1[:64])^T/16
__device__ float   d_ow2I[64 * 64];       // interleaved ow2^T
__device__ float   d_Px[32 * 64];         // separable grid-feat projections
__device__ float   d_Py[32 * 64];
__device__ float   d_Pz[32 * 64];         // includes ob1 + eb2@ow1[:64]

// center-outward column order (sorted by dx^2+dy^2)
__device__ const signed char COL_DX[25] =
    {0, 1,-1, 0, 0, 1, 1,-1,-1, 2,-2, 0, 0, 2, 2,-2,-2, 1, 1,-1,-1, 2, 2,-2,-2};
__device__ const signed char COL_DY[25] =
    {0, 0, 0, 1,-1, 1,-1, 1,-1, 0, 0, 2,-2, 1,-1, 1,-1, 2,-2, 2,-2, 2,-2, 2,-2};

// ---------------- helpers ---------------------------------------------------
__device__ __forceinline__ float ex2a(float x)  { float y; asm("ex2.approx.f32 %0,%1;" : "=f"(y) : "f"(x)); return y; }
__device__ __forceinline__ float rcpa(float x)  { float y; asm("rcp.approx.f32 %0,%1;" : "=f"(y) : "f"(x)); return y; }
__device__ __forceinline__ float rsqa(float x)  { float y; asm("rsqrt.approx.f32 %0,%1;" : "=f"(y) : "f"(x)); return y; }

// gelu_tanh(x) = x * (1 - 1/(2^(x*(2.3021181 + 0.10294919 x^2)) + 1))
__device__ __forceinline__ float gelu_fast(float x) {
    float x2  = x * x;
    float arg = x * fmaf(0.10294919f, x2, 2.3021181f);
    float r   = rcpa(ex2a(arg) + 1.0f);
    return fmaf(-x, r, x);
}

// ================= K_pre: precomputes + bin + per-point projections =========
__global__ void k_pre(const float* __restrict__ verts,
                      const float* __restrict__ feat,
                      const float* __restrict__ gfeat,
                      const float* __restrict__ ew1,
                      const float* __restrict__ eb1,
                      const float* __restrict__ ew2,
                      const float* __restrict__ eb2,
                      const float* __restrict__ ow1,
                      const float* __restrict__ ob1,
                      const float* __restrict__ ow2) {
    int b = blockIdx.x, tid = threadIdx.x;
    if (b < 32) {                          // bin points (cellCnt pre-zeroed)
        int i = b * 256 + tid;
        float x = verts[3 * i], y = verts[3 * i + 1], z = verts[3 * i + 2];
        int cx = min(max((int)(x * (float)CELLS), 0), CELLS - 1);
        int cy = min(max((int)(y * (float)CELLS), 0), CELLS - 1);
        int cz = min(max((int)(z * (float)CELLS), 0), CELLS - 1);
        int c = (cx * CELLS + cy) * CELLS + cz;
        d_cellOf[i] = c;
        d_rank[i]   = atomicAdd(&d_cellCnt[c], 1);
        return;
    }
    if (b == 32) {                         // 9 moment constants of ew1 rows 32-34
        if (tid < 9) {
            const float* rows[3] = {ew1 + 2048, ew1 + 2112, ew1 + 2176};
            float acc = 0.0f;
            if (tid < 3) {
                const float* r = rows[tid];
                for (int c = 0; c < 64; ++c) acc += r[c];
                acc *= (1.0f / 64.0f);
            } else if (tid < 6) {
                const float* r = rows[tid - 3];
                for (int c = 0; c < 64; ++c) acc += r[c] * r[c];
                acc *= (1.0f / 64.0f);
            } else {
                int a = (tid == 8) ? 1 : 0;
                int bb = (tid == 6) ? 1 : 2;
                for (int c = 0; c < 64; ++c) acc += rows[a][c] * rows[bb][c];
                acc *= (1.0f / 32.0f);     // 2/64
            }
            d_C[tid] = acc;
        }
        return;
    }
    if (b < 49) {       // W12I interleaved: thread(g,cc) step i4 reads float4 at
                        // ((g*4+i4)*64+cc)*4 ; element k = (ew2@ow1)[g*16+i4*4+k][cc]/16
        int idx = (b - 33) * 256 + tid;    // 0..4095
        int n = idx >> 2, k = idx & 3;
        int r = n >> 6, cc = n & 63;       // r = g*4+i4
        int i = r * 4 + k;                 // input-channel index
        float acc = 0.0f;
        for (int t = 0; t < 64; ++t)
            acc += ew2[i * 64 + t] * ow1[t * 64 + cc];
        d_W12I[idx] = acc * (1.0f / 16.0f);
        return;
    }
    if (b < 65) {                          // ow2 interleaved, same scheme
        int idx = (b - 49) * 256 + tid;
        int n = idx >> 2, k = idx & 3;
        int r = n >> 6, cc = n & 63;
        d_ow2I[idx] = ow2[(r * 4 + k) * 64 + cc];
        return;
    }
    if (b < 89) {                          // separable grid-feat projections
        int idx = (b - 65) * 256 + tid;    // 0..6143
        int axis = idx >> 11, r = (idx >> 6) & 31, c = idx & 63;
        int m0 = (axis == 0) ? r * 1024 : (axis == 1) ? r * 32 : r;
        const float* g = gfeat + m0 * 96 + axis * 32;
        float acc = 0.0f;
        for (int j = 0; j < 32; ++j)
            acc += g[j] * ow1[(64 + axis * 32 + j) * 64 + c];
        if (axis == 0)      d_Px[r * 64 + c] = acc;
        else if (axis == 1) d_Py[r * 64 + c] = acc;
        else {
            float s = ob1[c];
            for (int i = 0; i < 64; ++i) s += eb2[i] * ow1[i * 64 + c];
            d_Pz[r * 64 + c] = acc + s;
        }
        return;
    }
    // fp: warp per point — Fp projection (half2) + per-point LN moments
    int warp = tid >> 5, lane = tid & 31;
    int p = (b - 89) * 8 + warp;
    int c0 = 2 * lane, c1 = c0 + 1;
    float fl = __ldg(&feat[p * 32 + lane]);
    float acc0 = __ldg(&eb1[c0]), acc1 = __ldg(&eb1[c1]);
    #pragma unroll
    for (int i = 0; i < 32; ++i) {
        float fi = __shfl_sync(0xffffffffu, fl, i);
        acc0 = fmaf(fi, __ldg(&ew1[i * 64 + c0]), acc0);
        acc1 = fmaf(fi, __ldg(&ew1[i * 64 + c1]), acc1);
    }
    d_Fph[p * 32 + lane] = __floats2half2_rn(acc0, acc1);
    float A0 = __ldg(&ew1[2048 + c0]), A1 = __ldg(&ew1[2048 + c1]);
    float B0 = __ldg(&ew1[2112 + c0]), B1 = __ldg(&ew1[2112 + c1]);
    float C0 = __ldg(&ew1[2176 + c0]), C1 = __ldg(&ew1[2176 + c1]);
    float pF  = acc0 + acc1;
    float pFF = acc0 * acc0 + acc1 * acc1;
    float pA  = acc0 * A0 + acc1 * A1;
    float pB  = acc0 * B0 + acc1 * B1;
    float pC  = acc0 * C0 + acc1 * C1;
    #pragma unroll
    for (int o = 16; o > 0; o >>= 1) {
        pF  += __shfl_xor_sync(0xffffffffu, pF,  o);
        pFF += __shfl_xor_sync(0xffffffffu, pFF, o);
        pA  += __shfl_xor_sync(0xffffffffu, pA,  o);
        pB  += __shfl_xor_sync(0xffffffffu, pB,  o);
        pC  += __shfl_xor_sync(0xffffffffu, pC,  o);
    }
    if (lane == 0) {
        d_S0[p] = make_float4(__ldg(&verts[3 * p]), __ldg(&verts[3 * p + 1]),
                              __ldg(&verts[3 * p + 2]), pF * (1.0f / 64.0f));
        d_S1[p] = make_float4(pFF * (1.0f / 64.0f), pA * (1.0f / 32.0f),
                              pB * (1.0f / 32.0f),  pC * (1.0f / 32.0f));
    }
}

// =========== scan + scatter fused (1 block, 1024 threads) ===================
__global__ void k_scan_scatter(const float* __restrict__ verts) {
    __shared__ int sc[1024];
    int t = threadIdx.x;
    int c0 = d_cellCnt[4 * t + 0];
    int c1 = d_cellCnt[4 * t + 1];
    int c2 = d_cellCnt[4 * t + 2];
    int c3 = d_cellCnt[4 * t + 3];
    int ts = c0 + c1 + c2 + c3;
    sc[t] = ts;
    __syncthreads();
    for (int off = 1; off < 1024; off <<= 1) {
        int v = (t >= off) ? sc[t - off] : 0;
        __syncthreads();
        sc[t] += v;
        __syncthreads();
    }
    int base = sc[t] - ts;
    d_cellStart[4 * t + 0] = base;
    d_cellStart[4 * t + 1] = base + c0;
    d_cellStart[4 * t + 2] = base + c0 + c1;
    d_cellStart[4 * t + 3] = base + c0 + c1 + c2;
    if (t == 1023) d_cellStart[NCELL] = sc[1023];
    __syncthreads();
    #pragma unroll
    for (int r = 0; r < NPTS / 1024; ++r) {
        int i = r * 1024 + t;
        int dst = d_cellStart[d_cellOf[i]] + d_rank[i];
        d_pts[dst] = make_float4(verts[3 * i], verts[3 * i + 1],
                                 verts[3 * i + 2], __int_as_float(i));
    }
}

// ================= KNN ======================================================
// insert with replace-worst rescan
#define INS_(D_, W_)                                                       \
    if (D_ < worst) {                                                      \
        int id_ = __float_as_int(W_);                                      \
        float nw_ = -1.0f; int ns_ = 0;                                    \
        _Pragma("unroll")                                                  \
        for (int t_ = 0; t_ < KK; ++t_) {                                  \
            if (t_ == wslot) { bd[t_] = D_; bi[t_] = id_; }                \
            if (bd[t_] > nw_) { nw_ = bd[t_]; ns_ = t_; }                  \
        }                                                                  \
        worst = nw_; wslot = ns_;                                          \
    }

// chunk-4 scan: 4 independent loads issued in one basic block (MLP=4)
#define SCAN_RANGE(S_, E_)                                                 \
    {                                                                      \
        int j_ = (S_);                                                     \
        for (; j_ + 4 <= (E_); j_ += 4) {                                  \
            float4 pa_ = d_pts[j_];                                        \
            float4 pb_ = d_pts[j_ + 1];                                    \
            float4 pc_ = d_pts[j_ + 2];                                    \
            float4 pd_ = d_pts[j_ + 3];                                    \
            float dxa_ = pa_.x - qx, dya_ = pa_.y - qy, dza_ = pa_.z - qz; \
            float dxb_ = pb_.x - qx, dyb_ = pb_.y - qy, dzb_ = pb_.z - qz; \
            float dxc_ = pc_.x - qx, dyc_ = pc_.y - qy, dzc_ = pc_.z - qz; \
            float dxd_ = pd_.x - qx, dyd_ = pd_.y - qy, dzd_ = pd_.z - qz; \
            float da_ = dxa_*dxa_ + dya_*dya_ + dza_*dza_;                 \
            float db_ = dxb_*dxb_ + dyb_*dyb_ + dzb_*dzb_;                 \
            float dc_ = dxc_*dxc_ + dyc_*dyc_ + dzc_*dzc_;                 \
            float dd_ = dxd_*dxd_ + dyd_*dyd_ + dzd_*dzd_;                 \
            INS_(da_, pa_.w)                                               \
            INS_(db_, pb_.w)                                               \
            INS_(dc_, pc_.w)                                               \
            INS_(dd_, pd_.w)                                               \
        }                                                                  \
        for (; j_ < (E_); ++j_) {                                          \
            float4 pa_ = d_pts[j_];                                        \
            float dxa_ = pa_.x - qx, dya_ = pa_.y - qy, dza_ = pa_.z - qz; \
            float da_ = dxa_*dxa_ + dya_*dya_ + dza_*dza_;                 \
            INS_(da_, pa_.w)                                               \
        }                                                                  \
    }

__device__ __forceinline__ void knn_pass(float qx, float qy, float qz,
                                         int cx, int cy, int cz, float Tinit,
                                         float (&bd)[KK], int (&bi)[KK]) {
    #pragma unroll
    for (int t = 0; t < KK; ++t) { bd[t] = Tinit; bi[t] = -1; }
    float worst = Tinit;
    int   wslot = 0;
    const float h = 1.0f / (float)CELLS;

    // Phase 1: cheb-2 neighborhood as center-outward columns, each pruned by
    // its 2D min distance vs current worst (adaptive as worst shrinks).
    {
        int z0 = max(cz - 2, 0), z1e = min(cz + 2, CELLS - 1) + 1;
        #pragma unroll 1
        for (int ci = 0; ci < 25; ++ci) {
            int ax = cx + (int)COL_DX[ci];
            int ay = cy + (int)COL_DY[ci];
            if (ax < 0 || ax > CELLS - 1 || ay < 0 || ay > CELLS - 1) continue;
            float clx = ax * h, cly = ay * h;
            float ddx = fmaxf(fmaxf(clx - qx, qx - clx - h), 0.0f);
            float ddy = fmaxf(fmaxf(cly - qy, qy - cly - h), 0.0f);
            if (ddx * ddx + ddy * ddy >= worst) continue;
            int base = (ax * CELLS + ay) * CELLS;
            int s = d_cellStart[base + z0], e = d_cellStart[base + z1e];
            SCAN_RANGE(s, e)
        }
    }
    // Phase 2: ring expansion until provably complete
    int R = 2;
    while (worst > (R * h) * (R * h) && R < CELLS - 1) {
        ++R;
        int ax0 = max(cx - R, 0), ax1 = min(cx + R, CELLS - 1);
        int ay0 = max(cy - R, 0), ay1 = min(cy + R, CELLS - 1);
        for (int ax = ax0; ax <= ax1; ++ax)
            for (int ay = ay0; ay <= ay1; ++ay) {
                int cxy = max(abs(ax - cx), abs(ay - cy));
                int base = (ax * CELLS + ay) * CELLS;
                if (cxy == R) {
                    int s = d_cellStart[base + max(cz - R, 0)];
                    int e = d_cellStart[base + min(cz + R, CELLS - 1) + 1];
                    SCAN_RANGE(s, e)
                } else {
                    int zl = cz - R, zh = cz + R;
                    if (zl >= 0) {
                        int s = d_cellStart[base + zl], e = d_cellStart[base + zl + 1];
                        SCAN_RANGE(s, e)
                    }
                    if (zh <= CELLS - 1) {
                        int s = d_cellStart[base + zh], e = d_cellStart[base + zh + 1];
                        SCAN_RANGE(s, e)
                    }
                }
            }
    }
}

__global__ void __launch_bounds__(256) k_knn(const float* __restrict__ gverts) {
    int tid  = blockIdx.x * 256 + threadIdx.x;
    int W    = tid >> 5;
    int lane = tid & 31;
    int lx = lane & 3, ly = (lane >> 2) & 3, lz = lane >> 4;
    int tz = W & 15, ty = (W >> 4) & 7, tx = W >> 7;
    int X = tx * 4 + lx, Y = ty * 4 + ly, Z = tz * 2 + lz;
    int m = (X * 32 + Y) * 32 + Z;

    float qx = gverts[3 * m], qy = gverts[3 * m + 1], qz = gverts[3 * m + 2];
    int cx = min((int)(qx * (float)CELLS), CELLS - 1);
    int cy = min((int)(qy * (float)CELLS), CELLS - 1);
    int cz = min((int)(qz * (float)CELLS), CELLS - 1);

    // density-calibrated threshold, boundary-amplified per clipped axis
    float Tq = 0.010f;
    if (qx < 0.10f || qx > 0.90f) Tq *= 1.5874f;
    if (qy < 0.10f || qy > 0.90f) Tq *= 1.5874f;
    if (qz < 0.10f || qz > 0.90f) Tq *= 1.5874f;

    float bd[KK];
    int   bi[KK];
    // single code instance of knn_pass (retry loop) to keep reg pressure low
    #pragma unroll 1
    for (int attempt = 0; attempt < 2; ++attempt) {
        knn_pass(qx, qy, qz, cx, cy, cz, Tq, bd, bi);
        bool bad = false;
        #pragma unroll
        for (int t = 0; t < KK; ++t) bad |= (bi[t] < 0);
        if (!bad) break;
        Tq = 3.4e38f;
    }

    #pragma unroll
    for (int t = 0; t < KK; ++t) d_knn[m * KK + t] = bi[t];
}

// ================= fused MLP ================================================
__global__ void __launch_bounds__(256, 6) k_mlp(
    const float* __restrict__ gverts, const float* __restrict__ ew1,
    const float* __restrict__ eg1, const float* __restrict__ ebt1,
    const float* __restrict__ og1, const float* __restrict__ obt1,
    const float* __restrict__ ob2, float* __restrict__ out) {

    __shared__ float sAct[8][COUT];
    __shared__ float sPart[4][8][COUT];
    __shared__ float sEdge[8][KK][8];   // [warp][k][rx,ry,rz,mu,rs,jbits,-,-]

    int tid  = threadIdx.x;
    int warp = tid >> 5, lane = tid & 31;
    int m0 = blockIdx.x * 8;
    int m  = m0 + warp;
    int c0 = 2 * lane, c1 = c0 + 1;

    float qx = __ldg(&gverts[3 * m]);
    float qy = __ldg(&gverts[3 * m + 1]);
    float qz = __ldg(&gverts[3 * m + 2]);

    // ---- phase 0: per-edge moment precompute, one edge per lane (<16) ----
    if (lane < KK) {
        int j = __ldg(&d_knn[m * KK + lane]);
        float4 s0 = d_S0[j];
        float4 s1 = d_S1[j];
        float rx = s0.x - qx, ry = s0.y - qy, rz = s0.z - qz;
        float mu = s0.w + rx * d_C[0] + ry * d_C[1] + rz * d_C[2];
        float e2 = s1.x + rx * s1.y + ry * s1.z + rz * s1.w
                 + rx * (rx * d_C[3] + ry * d_C[6] + rz * d_C[7])
                 + ry * ry * d_C[4] + rz * (ry * d_C[8] + rz * d_C[5]);
        float rs = rsqa(e2 - mu * mu + 1e-5f);
        float* se = sEdge[warp][lane];
        se[0] = rx; se[1] = ry; se[2] = rz; se[3] = mu; se[4] = rs;
        ((int*)se)[5] = j;
    }
    __syncwarp();

    // ---- phase 1: edge loop (Fp in half2 — 1 wavefront per edge) ----
    float wp00 = __ldg(&ew1[2048 + c0]), wp01 = __ldg(&ew1[2048 + c1]);
    float wp10 = __ldg(&ew1[2112 + c0]), wp11 = __ldg(&ew1[2112 + c1]);
    float wp20 = __ldg(&ew1[2176 + c0]), wp21 = __ldg(&ew1[2176 + c1]);
    float ge0 = __ldg(&eg1[c0]),  ge1 = __ldg(&eg1[c1]);
    float gb0 = __ldg(&ebt1[c0]), gb1 = __ldg(&ebt1[c1]);

    float a0 = 0.0f, a1 = 0.0f;
    #pragma unroll 4
    for (int k = 0; k < KK; ++k) {
        const float* se = sEdge[warp][k];
        float4 v0 = *(const float4*)se;          // rx,ry,rz,mu
        float2 v1 = *(const float2*)(se + 4);    // rs, jbits
        int j = __float_as_int(v1.y);
        float2 f = __half22float2(d_Fph[j * 32 + lane]);
        float h0 = f.x + v0.x * wp00 + v0.y * wp10 + v0.z * wp20;
        float h1 = f.y + v0.x * wp01 + v0.y * wp11 + v0.z * wp21;
        float rsg0 = v1.x * ge0, rsg1 = v1.x * ge1;
        float n0 = fmaf(h0, rsg0, fmaf(-v0.w, rsg0, gb0));
        float n1 = fmaf(h1, rsg1, fmaf(-v0.w, rsg1, gb1));
        a0 += gelu_fast(n0);
        a1 += gelu_fast(n1);
    }
    sAct[warp][c0] = a0;
    sAct[warp][c1] = a1;
    __syncthreads();

    // R4 conflict-free mapping: g uniform per warp, cc consecutive
    int g = tid >> 6, cc = tid & 63;

    // ---- phase 2: block matvec @ W12I (interleaved; 512B contiguous/warp) --
    {
        float acc[8];
        #pragma unroll
        for (int q = 0; q < 8; ++q) acc[q] = 0.0f;
        #pragma unroll
        for (int i4 = 0; i4 < 4; ++i4) {
            float4 w = __ldg((const float4*)&d_W12I[((g * 4 + i4) * 64 + cc) * 4]);
            #pragma unroll
            for (int q = 0; q < 8; ++q) {
                float4 a = *(const float4*)&sAct[q][g * 16 + i4 * 4];
                acc[q] += a.x * w.x + a.y * w.y + a.z * w.z + a.w * w.w;
            }
        }
        #pragma unroll
        for (int q = 0; q < 8; ++q) sPart[g][q][cc] = acc[q];
    }
    __syncthreads();

    // ---- phase 3: combine + grid-feat tables + LN + gelu (warp per query) --
    {
        int X = m >> 10, Y = (m >> 5) & 31, Z = m & 31;
        float2 px = *(const float2*)&d_Px[X * 64 + c0];
        float2 py = *(const float2*)&d_Py[Y * 64 + c0];
        float2 pz = *(const float2*)&d_Pz[Z * 64 + c0];
        float o0 = px.x + py.x + pz.x
                 + sPart[0][warp][c0] + sPart[1][warp][c0]
                 + sPart[2][warp][c0] + sPart[3][warp][c0];
        float o1 = px.y + py.y + pz.y
                 + sPart[0][warp][c1] + sPart[1][warp][c1]
                 + sPart[2][warp][c1] + sPart[3][warp][c1];
        float s  = o0 + o1;
        float s2 = o0 * o0 + o1 * o1;
        #pragma unroll
        for (int o = 16; o > 0; o >>= 1) {
            s  += __shfl_xor_sync(0xffffffffu, s,  o);
            s2 += __shfl_xor_sync(0xffffffffu, s2, o);
        }
        float mu  = s * (1.0f / 64.0f);
        float var = s2 * (1.0f / 64.0f) - mu * mu;
        float rs  = rsqa(var + 1e-5f);
        float oge0 = __ldg(&og1[c0]),  oge1 = __ldg(&og1[c1]);
        float ogb0 = __ldg(&obt1[c0]), ogb1 = __ldg(&obt1[c1]);
        o0 = gelu_fast((o0 - mu) * rs * oge0 + ogb0);
        o1 = gelu_fast((o1 - mu) * rs * oge1 + ogb1);
        __syncthreads();
        sAct[warp][c0] = o0;
        sAct[warp][c1] = o1;
    }
    __syncthreads();

    // ---- phase 4: block matvec @ ow2I (interleaved) ----
    {
        float acc[8];
        #pragma unroll
        for (int q = 0; q < 8; ++q) acc[q] = 0.0f;
        #pragma unroll
        for (int i4 = 0; i4 < 4; ++i4) {
            float4 w = __ldg((const float4*)&d_ow2I[((g * 4 + i4) * 64 + cc) * 4]);
            #pragma unroll
            for (int q = 0; q < 8; ++q) {
                float4 a = *(const float4*)&sAct[q][g * 16 + i4 * 4];
                acc[q] += a.x * w.x + a.y * w.y + a.z * w.z + a.w * w.w;
            }
        }
        #pragma unroll
        for (int q = 0; q < 8; ++q) sPart[g][q][cc] = acc[q];
    }
    __syncthreads();

    // ---- phase 5: final combine + bias + store ----
    float bias = __ldg(&ob2[cc]);
    #pragma unroll
    for (int rep = 0; rep < 2; ++rep) {
        int q = g + rep * 4;
        float v = sPart[0][q][cc] + sPart[1][q][cc]
                + sPart[2][q][cc] + sPart[3][q][cc] + bias;
        out[(m0 + q) * 64 + cc] = v;
    }
}

// ---------------- launch -----------------------------------------------------
extern "C" void kernel_launch(void* const* d_in, const int* in_sizes, int n_in,
                              void* d_out, int out_size) {
    const float* vertices = (const float*)d_in[0];
    const float* features = (const float*)d_in[1];
    const float* gverts   = (const float*)d_in[2];
    const float* gfeat    = (const float*)d_in[3];
    const float* ew1      = (const float*)d_in[4];
    const float* eb1      = (const float*)d_in[5];
    const float* eg1      = (const float*)d_in[6];
    const float* ebt1     = (const float*)d_in[7];
    const float* ew2      = (const float*)d_in[8];
    const float* eb2      = (const float*)d_in[9];
    const float* ow1      = (const float*)d_in[10];
    const float* ob1      = (const float*)d_in[11];
    const float* og1      = (const float*)d_in[12];
    const float* obt1     = (const float*)d_in[13];
    const float* ow2      = (const float*)d_in[14];
    const float* ob2      = (const float*)d_in[15];
    float* out = (float*)d_out;

    void* cntPtr = nullptr;
    cudaGetSymbolAddress(&cntPtr, d_cellCnt);
    cudaMemsetAsync(cntPtr, 0, NCELL * sizeof(int));

    k_pre <<<89 + NPTS / 8, 256>>>(vertices, features, gfeat, ew1, eb1, ew2,
                                   eb2, ow1, ob1, ow2);
    k_scan_scatter<<<1, 1024>>>(vertices);
    k_knn <<<NQ / 256, 256>>>(gverts);
    k_mlp <<<NQ / 8, 256>>>(gverts, ew1, eg1, ebt1, og1, obt1, ob2, out);
}